// round 16
// baseline (speedup 1.0000x reference)
#include <cuda_runtime.h>
#include <cuda_fp16.h>
#include <cstdint>

// ---------------- problem constants ----------------
#define BATCH 2
#define CCH   256
#define NHEAD 8
#define HD    32
#define GRP   32
#define CPG   8
#define MQKV  768
#define NSP   32768
#define EPS   1e-5f
#define KVS   16       // kv splits, 2048 seq cols each (single wave)

// ---------------- static scratch ----------------
__device__ __half g_qkvh[(size_t)BATCH * MQKV * NSP];   // fp16 q|k|v
__device__ __half g_xh[(size_t)BATCH * CCH * NSP];      // fp16 x (raw)
__device__ __half g_projh[(size_t)BATCH * CCH * NSP];   // fp16 proj
__device__ __half g_a2h[(size_t)BATCH * MQKV * CCH];    // folded A' fp16
__device__ __half g_w2h[(size_t)BATCH * CCH * CCH];     // W2 fp16
__device__ float g_bias2[BATCH * MQKV];
__device__ float g_ksumA[BATCH * CCH];
__device__ float g_kvpart[(size_t)KVS * 16 * 1024];
__device__ float g_ksump[KVS * 16 * 32];
__device__ float g_kv[BATCH * NHEAD * HD * HD];
__device__ float g_gnpart[(size_t)BATCH * 256 * 64];
__device__ float g_gn1p[BATCH * GRP * 4 * 2];

// ---------------- helpers ----------------
__device__ __forceinline__ float warp_sum(float v) {
    #pragma unroll
    for (int o = 16; o; o >>= 1) v += __shfl_xor_sync(0xffffffffu, v, o);
    return v;
}
__device__ __forceinline__ uint32_t smem_u32(const void* p) {
    uint32_t a;
    asm("{ .reg .u64 t; cvta.to.shared.u64 t, %1; cvt.u32.u64 %0, t; }" : "=r"(a) : "l"(p));
    return a;
}
__device__ __forceinline__ void cp16(uint32_t saddr, const void* g) {
    asm volatile("cp.async.cg.shared.global [%0], [%1], 16;" :: "r"(saddr), "l"(g) : "memory");
}
__device__ __forceinline__ void cp_commit() {
    asm volatile("cp.async.commit_group;" ::: "memory");
}
__device__ __forceinline__ void cp_wait1() {
    asm volatile("cp.async.wait_group 1;" ::: "memory");
}
__device__ __forceinline__ void ldm_x4(uint32_t* r, uint32_t addr) {
    asm volatile("ldmatrix.sync.aligned.m8n8.x4.shared.b16 {%0,%1,%2,%3}, [%4];"
        : "=r"(r[0]), "=r"(r[1]), "=r"(r[2]), "=r"(r[3]) : "r"(addr));
}
__device__ __forceinline__ void ldm_x4_trans(uint32_t* r, uint32_t addr) {
    asm volatile("ldmatrix.sync.aligned.m8n8.x4.trans.shared.b16 {%0,%1,%2,%3}, [%4];"
        : "=r"(r[0]), "=r"(r[1]), "=r"(r[2]), "=r"(r[3]) : "r"(addr));
}
__device__ __forceinline__ void mma_fp16(float* c, const uint32_t* a, uint32_t b0, uint32_t b1) {
    asm volatile(
        "mma.sync.aligned.m16n8k16.row.col.f32.f16.f16.f32 "
        "{%0,%1,%2,%3}, {%4,%5,%6,%7}, {%8,%9}, {%0,%1,%2,%3};"
        : "+f"(c[0]), "+f"(c[1]), "+f"(c[2]), "+f"(c[3])
        : "r"(a[0]), "r"(a[1]), "r"(a[2]), "r"(a[3]), "r"(b0), "r"(b1));
}
__device__ __forceinline__ void st_cs_h2(__half* p, __half2 v) {
    asm volatile("st.global.cs.u32 [%0], %1;" :: "l"(p), "r"(*(uint32_t*)&v) : "memory");
}

// ---------------- group-norm stats over x, 4 blocks per group (also emits xh) ------
__global__ void gn_stats0_kernel(const float* __restrict__ xsrc) {
    int grp = blockIdx.x;
    int quarter = blockIdx.y;
    const int M4 = CPG * NSP / 4;
    const int Q4 = M4 / 4;
    const float4* base = (const float4*)(xsrc + (size_t)grp * CPG * NSP) + quarter * Q4;
    uint2* xh4 = (uint2*)(g_xh + (size_t)grp * CPG * NSP) + quarter * Q4;
    float s = 0.f, s2 = 0.f;
    for (int i = threadIdx.x; i < Q4; i += 256) {
        float4 v = base[i];
        s  += (v.x + v.y) + (v.z + v.w);
        s2 += v.x * v.x + v.y * v.y + v.z * v.z + v.w * v.w;
        __half2 h0 = __floats2half2_rn(v.x, v.y);
        __half2 h1 = __floats2half2_rn(v.z, v.w);
        uint2 u;
        u.x = *(uint32_t*)&h0;
        u.y = *(uint32_t*)&h1;
        xh4[i] = u;
    }
    __shared__ float sh[8], sh2[8];
    s = warp_sum(s); s2 = warp_sum(s2);
    int w = threadIdx.x >> 5, l = threadIdx.x & 31;
    if (l == 0) { sh[w] = s; sh2[w] = s2; }
    __syncthreads();
    if (w == 0) {
        s  = (l < 8) ? sh[l]  : 0.f;
        s2 = (l < 8) ? sh2[l] : 0.f;
        s = warp_sum(s); s2 = warp_sum(s2);
        if (l == 0) {
            g_gn1p[(grp * 4 + quarter) * 2]     = s;
            g_gn1p[(grp * 4 + quarter) * 2 + 1] = s2;
        }
    }
}

// fold GN1 affine into weights (GN1 stats finalized inline from partials)
__global__ void prep2_kernel(const float* __restrict__ qkv_w, const float* __restrict__ qkv_b,
                             const float* __restrict__ nw, const float* __restrict__ nb) {
    int o = blockIdx.x, b = blockIdx.y;
    int c = threadIdx.x;
    int grp4 = (b * GRP + c / CPG) * 4;
    float s = 0.f, s2 = 0.f;
    #pragma unroll
    for (int i = 0; i < 4; i++) {
        s  += g_gn1p[(grp4 + i) * 2];
        s2 += g_gn1p[(grp4 + i) * 2 + 1];
    }
    const float invn = 1.0f / (float)(CPG * NSP);
    float mu = s * invn;
    float r  = rsqrtf(s2 * invn - mu * mu + EPS);
    float sc = r * nw[c];
    float sh = nb[c] - mu * sc;
    float w  = qkv_w[o * CCH + c];
    g_a2h[((size_t)b * MQKV + o) * CCH + c] = __float2half_rn(w * sc);
    float v = w * sh;
    __shared__ float red[8];
    v = warp_sum(v);
    int wp = c >> 5, l = c & 31;
    if (l == 0) red[wp] = v;
    __syncthreads();
    if (c == 0) {
        float acc = 0.f;
        #pragma unroll
        for (int i = 0; i < 8; i++) acc += red[i];
        g_bias2[b * MQKV + o] = acc + qkv_b[o];
    }
}

// ======== fp16 GEMM: block-resident B (256x128), m-loop, K-chunks of 64, depth-2 ====
#define ABUF 16384
#define BFULL 65536
#define GSMEM (2 * ABUF + BFULL)

template<int MODE>
__global__ void __launch_bounds__(256, 2) mma_gemm_kernel(const float* __restrict__ bias_arg)
{
    extern __shared__ char smem[];
    const uint32_t sbase = smem_u32(smem);
    const uint32_t bOffB = 2u * ABUF;
    const int MT = (MODE == 0) ? 6 : 2;
    const int NG = MT * 4;

    __shared__ float gnacc[2][64];
    __shared__ float ksA_sm[256];
    __shared__ float normsm[1024];

    const int bz = blockIdx.z;
    const int nt = blockIdx.x;
    const int t  = threadIdx.x;
    const int warp = t >> 5, lane = t & 31;
    const int wm = warp >> 1;
    const int wn = warp & 1;
    const int g  = lane >> 2;
    const int c  = lane & 3;

    const __half* Ab0;
    const __half* Bb;
    const float* bias;
    if (MODE == 0) {
        Ab0  = g_a2h + (size_t)bz * MQKV * CCH;
        bias = g_bias2 + bz * MQKV;
        Bb   = g_xh + (size_t)bz * CCH * NSP + (size_t)nt * 128;
    } else {
        Ab0  = g_w2h + (size_t)bz * CCH * CCH;
        bias = bias_arg;
        Bb   = g_qkvh + (size_t)bz * MQKV * NSP + (size_t)nt * 128;
    }

    if (MODE == 1) {
        if (t < 128) gnacc[t >> 6][t & 63] = 0.f;
        ksA_sm[t] = g_ksumA[bz * CCH + t];
    }

    #pragma unroll
    for (int i = 0; i < 16; i++) {
        int f = t + i * 256;
        int k = f >> 4, cc = f & 15;
        cp16(sbase + bOffB + (uint32_t)(k * 256 + ((cc ^ (k & 7)) << 4)),
             Bb + (size_t)k * NSP + cc * 8);
    }
    cp_commit();

    const __half* aPtr = Ab0 + (size_t)(t >> 3) * CCH + (t & 7) * 8;
    const uint32_t aDstOff = (uint32_t)((t >> 3) * 128 + (((t & 7) ^ ((t >> 3) & 7)) << 4));
    int loadG = 0;
    auto load_A = [&]() {
        uint32_t d = sbase + (uint32_t)(loadG & 1) * ABUF + aDstOff;
        #pragma unroll
        for (int i = 0; i < 4; i++)
            cp16(d + (uint32_t)i * (32u * 128u), aPtr + (size_t)i * 32 * CCH);
        cp_commit();
        aPtr += ((loadG & 3) == 3) ? (128 * CCH - 192) : 64;
        loadG++;
    };
    load_A();
    load_A();

    uint32_t aAddrF[2];
    {
        int row_lo = (lane & 7) + ((lane >> 3) & 1) * 8;
        int kc = lane >> 4;
        #pragma unroll
        for (int i2 = 0; i2 < 2; i2++) {
            int row = wm * 32 + i2 * 16 + row_lo;
            aAddrF[i2] = (uint32_t)(row * 128 + ((kc ^ (row & 7)) << 4));
        }
    }
    uint32_t bAddrF;
    {
        int k  = (lane & 7) + ((lane >> 4) << 3);
        int nb = wn * 64 + ((lane >> 3) & 1) * 8;
        int cc = nb >> 3;
        bAddrF = (uint32_t)(k * 256 + ((cc ^ (k & 7)) << 4));
    }

    float acc[2][8][4];
    #pragma unroll
    for (int i = 0; i < 2; i++)
        #pragma unroll
        for (int j = 0; j < 8; j++)
            #pragma unroll
            for (int q = 0; q < 4; q++) acc[i][j][q] = 0.f;

    #pragma unroll 1
    for (int G = 0; G < NG; G++) {
        int kt = G & 3;
        int mt2 = G >> 2;
        int buf = G & 1;

        cp_wait1();
        __syncthreads();

        if (MODE == 1 && G == 0) {
            #pragma unroll
            for (int u = 0; u < 2; u++) {
                int idx = u * 256 + t;
                int h = idx >> 6, n2 = idx & 63;
                int col0 = n2 * 2;
                int cc = col0 >> 3, off = (col0 & 7) * 2;
                float sx = 0.f, sy = 0.f;
                #pragma unroll
                for (int d = 0; d < 32; d++) {
                    int r = h * 32 + d;
                    const __half2* p = (const __half2*)(smem + bOffB
                        + r * 256 + ((cc ^ (r & 7)) << 4) + off);
                    float2 v = __half22float2(*p);
                    float ka = ksA_sm[r];
                    sx = fmaf(v.x, ka, sx);
                    sy = fmaf(v.y, ka, sy);
                }
                normsm[h * 128 + col0]     = 1.0f / fmaxf(sx, 1e-6f);
                normsm[h * 128 + col0 + 1] = 1.0f / fmaxf(sy, 1e-6f);
            }
            __syncthreads();
            #pragma unroll
            for (int u = 0; u < 64; u++) {
                int idx = u * 256 + t;
                int r = idx >> 6, n2 = idx & 63;
                int col0 = n2 * 2;
                int cc = col0 >> 3;
                __half2* p = (__half2*)(smem + bOffB
                    + r * 256 + ((cc ^ (r & 7)) << 4) + (col0 & 7) * 2);
                float2 v = __half22float2(*p);
                int h = r >> 5;
                v.x *= normsm[h * 128 + col0];
                v.y *= normsm[h * 128 + col0 + 1];
                *p = __floats2half2_rn(v.x, v.y);
            }
            __syncthreads();
        }

        uint32_t aB = sbase + (uint32_t)buf * ABUF;
        uint32_t bB = sbase + bOffB + (uint32_t)kt * 16384;
        #pragma unroll
        for (int kg = 0; kg < 4; kg++) {
            uint32_t afr[2][4];
            #pragma unroll
            for (int i2 = 0; i2 < 2; i2++)
                ldm_x4(afr[i2], aB + (aAddrF[i2] ^ (kg << 5)));
            uint32_t bfr[4][4];
            #pragma unroll
            for (int j4 = 0; j4 < 4; j4++)
                ldm_x4_trans(bfr[j4], bB + ((bAddrF ^ (j4 << 5)) + (kg << 12)));
            #pragma unroll
            for (int j2 = 0; j2 < 8; j2++) {
                uint32_t b0 = bfr[j2 >> 1][(j2 & 1)];
                uint32_t b1 = bfr[j2 >> 1][(j2 & 1) + 2];
                #pragma unroll
                for (int i2 = 0; i2 < 2; i2++)
                    mma_fp16(acc[i2][j2], afr[i2], b0, b1);
            }
        }

        if (kt == 3) {
            #pragma unroll
            for (int i2 = 0; i2 < 2; i2++) {
                int lr0 = wm * 32 + i2 * 16 + g;
                int o0  = mt2 * 128 + lr0;
                int o1  = o0 + 8;
                float bi0 = bias[o0], bi1 = bias[o1];
                float slo = 0.f, slo2 = 0.f, shi = 0.f, shi2 = 0.f;
                #pragma unroll
                for (int j2 = 0; j2 < 8; j2++) {
                    int lc = wn * 64 + j2 * 8 + 2 * c;
                    float v0 = acc[i2][j2][0] + bi0;
                    float v1 = acc[i2][j2][1] + bi0;
                    float v2 = acc[i2][j2][2] + bi1;
                    float v3 = acc[i2][j2][3] + bi1;
                    if (MODE == 0) {
                        if (o0 < 512) {
                            v0 = (v0 > 0.f) ? (v0 + 1.f) : __expf(v0);
                            v1 = (v1 > 0.f) ? (v1 + 1.f) : __expf(v1);
                        }
                        if (o1 < 512) {
                            v2 = (v2 > 0.f) ? (v2 + 1.f) : __expf(v2);
                            v3 = (v3 > 0.f) ? (v3 + 1.f) : __expf(v3);
                        }
                        __half* Cd = g_qkvh + ((size_t)bz * MQKV + (size_t)mt2 * 128) * NSP
                                   + (size_t)nt * 128;
                        __half2 h01 = __floats2half2_rn(v0, v1);
                        __half2 h23 = __floats2half2_rn(v2, v3);
                        if (mt2 < 2) {
                            // q region: evict-first, keep k/v resident in L2 for kv_mma
                            st_cs_h2(Cd + (size_t)lr0 * NSP + lc, h01);
                            st_cs_h2(Cd + (size_t)(lr0 + 8) * NSP + lc, h23);
                        } else {
                            *(__half2*)(Cd + (size_t)lr0 * NSP + lc)       = h01;
                            *(__half2*)(Cd + (size_t)(lr0 + 8) * NSP + lc) = h23;
                        }
                    } else {
                        __half* Cd = g_projh + ((size_t)bz * CCH + (size_t)mt2 * 128) * NSP
                                   + (size_t)nt * 128;
                        *(__half2*)(Cd + (size_t)lr0 * NSP + lc)       = __floats2half2_rn(v0, v1);
                        *(__half2*)(Cd + (size_t)(lr0 + 8) * NSP + lc) = __floats2half2_rn(v2, v3);
                        slo += v0 + v1;  slo2 += v0 * v0 + v1 * v1;
                        shi += v2 + v3;  shi2 += v2 * v2 + v3 * v3;
                    }
                    #pragma unroll
                    for (int q = 0; q < 4; q++) acc[i2][j2][q] = 0.f;
                }
                if (MODE == 1) {
                    slo = warp_sum(slo);  slo2 = warp_sum(slo2);
                    shi = warp_sum(shi);  shi2 = warp_sum(shi2);
                    if (lane == 0) {
                        int Gi = mt2 * 16 + wm * 4 + i2 * 2;
                        gnacc[wn][Gi * 2]           += slo;
                        gnacc[wn][Gi * 2 + 1]       += slo2;
                        gnacc[wn][(Gi + 1) * 2]     += shi;
                        gnacc[wn][(Gi + 1) * 2 + 1] += shi2;
                    }
                }
            }
        }

        __syncthreads();
        if (G + 2 < NG) load_A();
        else            cp_commit();
    }

    if (MODE == 1) {
        __syncthreads();
        if (t < 64)
            g_gnpart[((size_t)bz * 256 + nt) * 64 + t] = gnacc[0][t] + gnacc[1][t];
    }
}

// ---------------- kv = k·v^T via tensor cores, single-wave grid, 8-slice pipeline ----
#define KVSLICE 16896
#define KVSTAGE (2 * KVSLICE)
#define KVSMEM  (2 * KVSTAGE)

__global__ void __launch_bounds__(256, 2) kv_mma_kernel() {
    extern __shared__ char sm[];
    const uint32_t sb = smem_u32(sm);

    int bh = blockIdx.x, split = blockIdx.y;
    int b = bh >> 3, h = bh & 7;

    const int t = threadIdx.x;
    const int lane = t & 31, w = t >> 5;
    const int g = lane >> 2, c = lane & 3;

    const __half* kbase = g_qkvh + ((size_t)b * MQKV + 256 + h * HD) * NSP + (size_t)split * 2048;
    const __half* vbase = g_qkvh + ((size_t)b * MQKV + 512 + h * HD) * NSP + (size_t)split * 2048;

    auto load_slice = [&](int sl) {
        int st = sl & 1;
        uint32_t kd = sb + (uint32_t)st * KVSTAGE;
        uint32_t vd = kd + KVSLICE;
        #pragma unroll
        for (int i = 0; i < 4; i++) {
            int f = t + i * 256;
            int r = f >> 5, c32 = f & 31;
            cp16(kd + (uint32_t)(r * 528 + c32 * 16),
                 kbase + (size_t)r * NSP + sl * 256 + c32 * 8);
            cp16(vd + (uint32_t)(r * 528 + c32 * 16),
                 vbase + (size_t)r * NSP + sl * 256 + c32 * 8);
        }
        cp_commit();
    };
    load_slice(0);
    load_slice(1);

    int row_lo = (lane & 7) + ((lane >> 3) & 1) * 8;
    int ksel = lane >> 4;
    uint32_t kbyte = (uint32_t)(w * 64 + ksel * 16);

    float acc[2][4][4];
    #pragma unroll
    for (int i = 0; i < 2; i++)
        #pragma unroll
        for (int j = 0; j < 4; j++)
            #pragma unroll
            for (int q = 0; q < 4; q++) acc[i][j][q] = 0.f;
    float rsum = 0.f;
    const int rr = t >> 3, seg = t & 7;

    #pragma unroll 1
    for (int sl = 0; sl < 8; sl++) {
        int st = sl & 1;
        uint32_t kB = sb + (uint32_t)st * KVSTAGE;
        uint32_t vB = kB + KVSLICE;

        cp_wait1();
        __syncthreads();

        const __half* krow = (const __half*)(sm + (size_t)st * KVSTAGE) + rr * 264;
        #pragma unroll
        for (int j = 0; j < 16; j++) {
            float2 kf = __half22float2(*(const __half2*)(krow + seg * 32 + 2 * j));
            rsum += kf.x + kf.y;
        }

        #pragma unroll
        for (int kg = 0; kg < 2; kg++) {
            uint32_t afr[2][4], bfr[2][4];
            #pragma unroll
            for (int i2 = 0; i2 < 2; i2++)
                ldm_x4(afr[i2], kB + (uint32_t)((i2 * 16 + row_lo) * 528) + kbyte + kg * 32);
            #pragma unroll
            for (int j4 = 0; j4 < 2; j4++)
                ldm_x4(bfr[j4], vB + (uint32_t)((j4 * 16 + row_lo) * 528) + kbyte + kg * 32);
            #pragma unroll
            for (int j = 0; j < 4; j++) {
                uint32_t b0 = bfr[j >> 1][(j & 1)];
                uint32_t b1 = bfr[j >> 1][(j & 1) + 2];
                #pragma unroll
                for (int i2 = 0; i2 < 2; i2++)
                    mma_fp16(acc[i2][j], afr[i2], b0, b1);
            }
        }

        __syncthreads();
        if (sl + 2 < 8) load_slice(sl + 2);
        else            cp_commit();
    }

    {
        float s = rsum;
        #pragma unroll
        for (int o = 4; o; o >>= 1) s += __shfl_xor_sync(0xffffffffu, s, o);
        if (seg == 0) g_ksump[(split * 16 + bh) * 32 + rr] = s;
    }
    __syncthreads();

    float* red = (float*)sm;
    #pragma unroll
    for (int i2 = 0; i2 < 2; i2++)
        #pragma unroll
        for (int j = 0; j < 4; j++) {
            int r0 = i2 * 16 + g, cc = j * 8 + 2 * c;
            red[w * 1024 + r0 * 32 + cc]           = acc[i2][j][0];
            red[w * 1024 + r0 * 32 + cc + 1]       = acc[i2][j][1];
            red[w * 1024 + (r0 + 8) * 32 + cc]     = acc[i2][j][2];
            red[w * 1024 + (r0 + 8) * 32 + cc + 1] = acc[i2][j][3];
        }
    __syncthreads();

    #pragma unroll
    for (int u = 0; u < 4; u++) {
        int de = t * 4 + u;
        float s = 0.f;
        #pragma unroll
        for (int ww = 0; ww < 8; ww++) s += red[ww * 1024 + de];
        g_kvpart[((size_t)split * 16 + bh) * 1024 + de] = s;
    }
}

// reduce kv partials + rowsums
__global__ void kvreduce_kernel() {
    int i = blockIdx.x * 256 + threadIdx.x;
    if (i >= 16 * 1024) return;
    int bh = i >> 10, de = i & 1023;
    int d = de >> 5, e = de & 31;
    float rs = 0.f;
    #pragma unroll
    for (int sp = 0; sp < KVS; sp++)
        rs += g_ksump[(sp * 16 + bh) * 32 + d];
    float cs = fmaxf(rs, 1e-6f);
    float inv = 1.0f / cs;
    float s = 0.f;
    #pragma unroll
    for (int sp = 0; sp < KVS; sp++)
        s += g_kvpart[((size_t)sp * 16 + bh) * 1024 + de];
    g_kv[i] = s * inv;
    if (e == 0) {
        int b = bh >> 3, h = bh & 7;
        g_ksumA[b * CCH + h * HD + d] = rs * inv;
    }
}

// ---------------- W2 = ow @ blockdiag(kv)^T ----------------
__global__ void w2prep_kernel(const float* __restrict__ out_w) {
    int o = blockIdx.x, b = blockIdx.y;
    int t = threadIdx.x;
    __shared__ float owrow[256];
    owrow[t] = out_w[o * CCH + t];
    __syncthreads();
    int h = t >> 5, d = t & 31;
    const float* kvp = g_kv + (b * 8 + h) * 1024 + d * 32;
    const float* owp = owrow + h * 32;
    float s = 0.f;
    #pragma unroll
    for (int e = 0; e < 32; e++) s = fmaf(owp[e], kvp[e], s);
    g_w2h[((size_t)b * CCH + o) * CCH + t] = __float2half_rn(s);
}

// ---------------- final: y = xh + GN2(proj), GN2 stats inline ----------------
__global__ void __launch_bounds__(256) final_kernel(
    const float* __restrict__ ow, const float* __restrict__ ob,
    float* __restrict__ out)
{
    const int n4 = NSP / 4;
    size_t base = (size_t)blockIdx.x * 1024;
    int row = (int)(base / n4);
    int c = row % CCH, b = row / CCH;
    int gg = c / CPG;

    float s  = g_gnpart[((size_t)b * 256 + threadIdx.x) * 64 + gg * 2];
    float s2 = g_gnpart[((size_t)b * 256 + threadIdx.x) * 64 + gg * 2 + 1];
    __shared__ float sh1[8], sh2[8];
    __shared__ float bc[2];
    s = warp_sum(s); s2 = warp_sum(s2);
    int w = threadIdx.x >> 5, l = threadIdx.x & 31;
    if (l == 0) { sh1[w] = s; sh2[w] = s2; }
    __syncthreads();
    if (threadIdx.x == 0) {
        float ts = 0.f, ts2 = 0.f;
        #pragma unroll
        for (int i = 0; i < 8; i++) { ts += sh1[i]; ts2 += sh2[i]; }
        const float invn = 1.0f / (float)(CPG * NSP);
        float mu = ts * invn;
        float r  = rsqrtf(ts2 * invn - mu * mu + EPS);
        float sc = r * ow[c];
        bc[0] = sc;
        bc[1] = ob[c] - mu * sc;
    }
    __syncthreads();
    float sc = bc[0], shf = bc[1];

    const __half2* ph = (const __half2*)g_projh;
    const __half2* xh = (const __half2*)g_xh;
    #pragma unroll
    for (int u = 0; u < 4; u++) {
        size_t i = base + u * 256 + threadIdx.x;
        float2 x0 = __half22float2(xh[2 * i]);
        float2 x1 = __half22float2(xh[2 * i + 1]);
        float2 p0 = __half22float2(ph[2 * i]);
        float2 p1 = __half22float2(ph[2 * i + 1]);
        float4 o;
        o.x = x0.x + fmaf(p0.x, sc, shf);
        o.y = x0.y + fmaf(p0.y, sc, shf);
        o.z = x1.x + fmaf(p1.x, sc, shf);
        o.w = x1.y + fmaf(p1.y, sc, shf);
        ((float4*)out)[i] = o;
    }
}

// ---------------- launch ----------------
extern "C" void kernel_launch(void* const* d_in, const int* in_sizes, int n_in,
                              void* d_out, int out_size) {
    const float* x      = (const float*)d_in[0];
    const float* norm_w = (const float*)d_in[1];
    const float* norm_b = (const float*)d_in[2];
    const float* qkv_w  = (const float*)d_in[3];
    const float* qkv_b  = (const float*)d_in[4];
    const float* out_w  = (const float*)d_in[5];
    const float* out_b  = (const float*)d_in[6];
    const float* onw    = (const float*)d_in[7];
    const float* onb    = (const float*)d_in[8];
    float* out = (float*)d_out;

    cudaFuncSetAttribute(mma_gemm_kernel<0>, cudaFuncAttributeMaxDynamicSharedMemorySize, GSMEM);
    cudaFuncSetAttribute(mma_gemm_kernel<1>, cudaFuncAttributeMaxDynamicSharedMemorySize, GSMEM);
    cudaFuncSetAttribute(kv_mma_kernel, cudaFuncAttributeMaxDynamicSharedMemorySize, KVSMEM);

    gn_stats0_kernel<<<dim3(BATCH * GRP, 4), 256>>>(x);
    prep2_kernel<<<dim3(MQKV, BATCH), 256>>>(qkv_w, qkv_b, norm_w, norm_b);
    mma_gemm_kernel<0><<<dim3(256, 1, BATCH), 256, GSMEM>>>(nullptr);
    kv_mma_kernel<<<dim3(16, KVS), 256, KVSMEM>>>();
    kvreduce_kernel<<<64, 256>>>();
    w2prep_kernel<<<dim3(CCH, BATCH), 256>>>(out_w);
    mma_gemm_kernel<1><<<dim3(256, 1, BATCH), 256, GSMEM>>>(out_b);
    final_kernel<<<4096, 256>>>(onw, onb, out);
}

// round 17
// speedup vs baseline: 1.0210x; 1.0210x over previous
#include <cuda_runtime.h>
#include <cuda_fp16.h>
#include <cstdint>

// ---------------- problem constants ----------------
#define BATCH 2
#define CCH   256
#define NHEAD 8
#define HD    32
#define GRP   32
#define CPG   8
#define MQKV  768
#define NSP   32768
#define EPS   1e-5f
#define KVS   16       // kv splits, 2048 seq cols each (single wave)

// ---------------- static scratch ----------------
__device__ __half g_qkvh[(size_t)BATCH * MQKV * NSP];   // fp16 q|k|v
__device__ __half g_xh[(size_t)BATCH * CCH * NSP];      // fp16 x (raw)
__device__ __half g_projh[(size_t)BATCH * CCH * NSP];   // fp16 proj
__device__ __half g_a2h[(size_t)BATCH * MQKV * CCH];    // folded A' fp16
__device__ __half g_w2h[(size_t)BATCH * CCH * CCH];     // W2 fp16
__device__ float g_bias2[BATCH * MQKV];
__device__ float g_ksumA[BATCH * CCH];
__device__ float g_kvpart[(size_t)KVS * 16 * 1024];
__device__ float g_ksump[KVS * 16 * 32];
__device__ float g_kv[BATCH * NHEAD * HD * HD];
__device__ float g_gnpart[(size_t)BATCH * 256 * 64];
__device__ float g_gn1p[BATCH * GRP * 4 * 2];

// ---------------- helpers ----------------
__device__ __forceinline__ float warp_sum(float v) {
    #pragma unroll
    for (int o = 16; o; o >>= 1) v += __shfl_xor_sync(0xffffffffu, v, o);
    return v;
}
__device__ __forceinline__ uint32_t smem_u32(const void* p) {
    uint32_t a;
    asm("{ .reg .u64 t; cvta.to.shared.u64 t, %1; cvt.u32.u64 %0, t; }" : "=r"(a) : "l"(p));
    return a;
}
__device__ __forceinline__ void cp16(uint32_t saddr, const void* g) {
    asm volatile("cp.async.cg.shared.global [%0], [%1], 16;" :: "r"(saddr), "l"(g) : "memory");
}
__device__ __forceinline__ void cp_commit() {
    asm volatile("cp.async.commit_group;" ::: "memory");
}
__device__ __forceinline__ void cp_wait1() {
    asm volatile("cp.async.wait_group 1;" ::: "memory");
}
__device__ __forceinline__ void ldm_x4(uint32_t* r, uint32_t addr) {
    asm volatile("ldmatrix.sync.aligned.m8n8.x4.shared.b16 {%0,%1,%2,%3}, [%4];"
        : "=r"(r[0]), "=r"(r[1]), "=r"(r[2]), "=r"(r[3]) : "r"(addr));
}
__device__ __forceinline__ void ldm_x4_trans(uint32_t* r, uint32_t addr) {
    asm volatile("ldmatrix.sync.aligned.m8n8.x4.trans.shared.b16 {%0,%1,%2,%3}, [%4];"
        : "=r"(r[0]), "=r"(r[1]), "=r"(r[2]), "=r"(r[3]) : "r"(addr));
}
__device__ __forceinline__ void mma_fp16(float* c, const uint32_t* a, uint32_t b0, uint32_t b1) {
    asm volatile(
        "mma.sync.aligned.m16n8k16.row.col.f32.f16.f16.f32 "
        "{%0,%1,%2,%3}, {%4,%5,%6,%7}, {%8,%9}, {%0,%1,%2,%3};"
        : "+f"(c[0]), "+f"(c[1]), "+f"(c[2]), "+f"(c[3])
        : "r"(a[0]), "r"(a[1]), "r"(a[2]), "r"(a[3]), "r"(b0), "r"(b1));
}

// ---------------- group-norm stats over x, 4 blocks per group (also emits xh) ------
__global__ void gn_stats0_kernel(const float* __restrict__ xsrc) {
    int grp = blockIdx.x;
    int quarter = blockIdx.y;
    const int M4 = CPG * NSP / 4;
    const int Q4 = M4 / 4;
    const float4* base = (const float4*)(xsrc + (size_t)grp * CPG * NSP) + quarter * Q4;
    uint2* xh4 = (uint2*)(g_xh + (size_t)grp * CPG * NSP) + quarter * Q4;
    float s = 0.f, s2 = 0.f;
    for (int i = threadIdx.x; i < Q4; i += 256) {
        float4 v = base[i];
        s  += (v.x + v.y) + (v.z + v.w);
        s2 += v.x * v.x + v.y * v.y + v.z * v.z + v.w * v.w;
        __half2 h0 = __floats2half2_rn(v.x, v.y);
        __half2 h1 = __floats2half2_rn(v.z, v.w);
        uint2 u;
        u.x = *(uint32_t*)&h0;
        u.y = *(uint32_t*)&h1;
        xh4[i] = u;
    }
    __shared__ float sh[8], sh2[8];
    s = warp_sum(s); s2 = warp_sum(s2);
    int w = threadIdx.x >> 5, l = threadIdx.x & 31;
    if (l == 0) { sh[w] = s; sh2[w] = s2; }
    __syncthreads();
    if (w == 0) {
        s  = (l < 8) ? sh[l]  : 0.f;
        s2 = (l < 8) ? sh2[l] : 0.f;
        s = warp_sum(s); s2 = warp_sum(s2);
        if (l == 0) {
            g_gn1p[(grp * 4 + quarter) * 2]     = s;
            g_gn1p[(grp * 4 + quarter) * 2 + 1] = s2;
        }
    }
}

// fold GN1 affine into weights (GN1 stats finalized inline from partials)
__global__ void prep2_kernel(const float* __restrict__ qkv_w, const float* __restrict__ qkv_b,
                             const float* __restrict__ nw, const float* __restrict__ nb) {
    int o = blockIdx.x, b = blockIdx.y;
    int c = threadIdx.x;
    int grp4 = (b * GRP + c / CPG) * 4;
    float s = 0.f, s2 = 0.f;
    #pragma unroll
    for (int i = 0; i < 4; i++) {
        s  += g_gn1p[(grp4 + i) * 2];
        s2 += g_gn1p[(grp4 + i) * 2 + 1];
    }
    const float invn = 1.0f / (float)(CPG * NSP);
    float mu = s * invn;
    float r  = rsqrtf(s2 * invn - mu * mu + EPS);
    float sc = r * nw[c];
    float sh = nb[c] - mu * sc;
    float w  = qkv_w[o * CCH + c];
    g_a2h[((size_t)b * MQKV + o) * CCH + c] = __float2half_rn(w * sc);
    float v = w * sh;
    __shared__ float red[8];
    v = warp_sum(v);
    int wp = c >> 5, l = c & 31;
    if (l == 0) red[wp] = v;
    __syncthreads();
    if (c == 0) {
        float acc = 0.f;
        #pragma unroll
        for (int i = 0; i < 8; i++) acc += red[i];
        g_bias2[b * MQKV + o] = acc + qkv_b[o];
    }
}

// ======== fp16 GEMM: block-resident B (256x128), m-loop, K-chunks of 64, depth-2 ====
#define ABUF 16384
#define BFULL 65536
#define GSMEM (2 * ABUF + BFULL)

template<int MODE>
__global__ void __launch_bounds__(256, 2) mma_gemm_kernel(const float* __restrict__ bias_arg)
{
    extern __shared__ char smem[];
    const uint32_t sbase = smem_u32(smem);
    const uint32_t bOffB = 2u * ABUF;
    const int MT = (MODE == 0) ? 6 : 2;
    const int NG = MT * 4;

    __shared__ float gnacc[2][64];
    __shared__ float ksA_sm[256];
    __shared__ float normsm[1024];

    const int bz = blockIdx.z;
    const int nt = blockIdx.x;
    const int t  = threadIdx.x;
    const int warp = t >> 5, lane = t & 31;
    const int wm = warp >> 1;
    const int wn = warp & 1;
    const int g  = lane >> 2;
    const int c  = lane & 3;

    const __half* Ab0;
    const __half* Bb;
    const float* bias;
    if (MODE == 0) {
        Ab0  = g_a2h + (size_t)bz * MQKV * CCH;
        bias = g_bias2 + bz * MQKV;
        Bb   = g_xh + (size_t)bz * CCH * NSP + (size_t)nt * 128;
    } else {
        Ab0  = g_w2h + (size_t)bz * CCH * CCH;
        bias = bias_arg;
        Bb   = g_qkvh + (size_t)bz * MQKV * NSP + (size_t)nt * 128;
    }

    if (MODE == 1) {
        if (t < 128) gnacc[t >> 6][t & 63] = 0.f;
        ksA_sm[t] = g_ksumA[bz * CCH + t];
    }

    #pragma unroll
    for (int i = 0; i < 16; i++) {
        int f = t + i * 256;
        int k = f >> 4, cc = f & 15;
        cp16(sbase + bOffB + (uint32_t)(k * 256 + ((cc ^ (k & 7)) << 4)),
             Bb + (size_t)k * NSP + cc * 8);
    }
    cp_commit();

    const __half* aPtr = Ab0 + (size_t)(t >> 3) * CCH + (t & 7) * 8;
    const uint32_t aDstOff = (uint32_t)((t >> 3) * 128 + (((t & 7) ^ ((t >> 3) & 7)) << 4));
    int loadG = 0;
    auto load_A = [&]() {
        uint32_t d = sbase + (uint32_t)(loadG & 1) * ABUF + aDstOff;
        #pragma unroll
        for (int i = 0; i < 4; i++)
            cp16(d + (uint32_t)i * (32u * 128u), aPtr + (size_t)i * 32 * CCH);
        cp_commit();
        aPtr += ((loadG & 3) == 3) ? (128 * CCH - 192) : 64;
        loadG++;
    };
    load_A();
    load_A();

    uint32_t aAddrF[2];
    {
        int row_lo = (lane & 7) + ((lane >> 3) & 1) * 8;
        int kc = lane >> 4;
        #pragma unroll
        for (int i2 = 0; i2 < 2; i2++) {
            int row = wm * 32 + i2 * 16 + row_lo;
            aAddrF[i2] = (uint32_t)(row * 128 + ((kc ^ (row & 7)) << 4));
        }
    }
    uint32_t bAddrF;
    {
        int k  = (lane & 7) + ((lane >> 4) << 3);
        int nb = wn * 64 + ((lane >> 3) & 1) * 8;
        int cc = nb >> 3;
        bAddrF = (uint32_t)(k * 256 + ((cc ^ (k & 7)) << 4));
    }

    float acc[2][8][4];
    #pragma unroll
    for (int i = 0; i < 2; i++)
        #pragma unroll
        for (int j = 0; j < 8; j++)
            #pragma unroll
            for (int q = 0; q < 4; q++) acc[i][j][q] = 0.f;

    #pragma unroll 1
    for (int G = 0; G < NG; G++) {
        int kt = G & 3;
        int mt2 = G >> 2;
        int buf = G & 1;

        cp_wait1();
        __syncthreads();

        if (MODE == 1 && G == 0) {
            #pragma unroll
            for (int u = 0; u < 2; u++) {
                int idx = u * 256 + t;
                int h = idx >> 6, n2 = idx & 63;
                int col0 = n2 * 2;
                int cc = col0 >> 3, off = (col0 & 7) * 2;
                float sx = 0.f, sy = 0.f;
                #pragma unroll
                for (int d = 0; d < 32; d++) {
                    int r = h * 32 + d;
                    const __half2* p = (const __half2*)(smem + bOffB
                        + r * 256 + ((cc ^ (r & 7)) << 4) + off);
                    float2 v = __half22float2(*p);
                    float ka = ksA_sm[r];
                    sx = fmaf(v.x, ka, sx);
                    sy = fmaf(v.y, ka, sy);
                }
                normsm[h * 128 + col0]     = 1.0f / fmaxf(sx, 1e-6f);
                normsm[h * 128 + col0 + 1] = 1.0f / fmaxf(sy, 1e-6f);
            }
            __syncthreads();
            #pragma unroll
            for (int u = 0; u < 64; u++) {
                int idx = u * 256 + t;
                int r = idx >> 6, n2 = idx & 63;
                int col0 = n2 * 2;
                int cc = col0 >> 3;
                __half2* p = (__half2*)(smem + bOffB
                    + r * 256 + ((cc ^ (r & 7)) << 4) + (col0 & 7) * 2);
                float2 v = __half22float2(*p);
                int h = r >> 5;
                v.x *= normsm[h * 128 + col0];
                v.y *= normsm[h * 128 + col0 + 1];
                *p = __floats2half2_rn(v.x, v.y);
            }
            __syncthreads();
        }

        uint32_t aB = sbase + (uint32_t)buf * ABUF;
        uint32_t bB = sbase + bOffB + (uint32_t)kt * 16384;
        #pragma unroll
        for (int kg = 0; kg < 4; kg++) {
            uint32_t afr[2][4];
            #pragma unroll
            for (int i2 = 0; i2 < 2; i2++)
                ldm_x4(afr[i2], aB + (aAddrF[i2] ^ (kg << 5)));
            uint32_t bfr[4][4];
            #pragma unroll
            for (int j4 = 0; j4 < 4; j4++)
                ldm_x4_trans(bfr[j4], bB + ((bAddrF ^ (j4 << 5)) + (kg << 12)));
            #pragma unroll
            for (int j2 = 0; j2 < 8; j2++) {
                uint32_t b0 = bfr[j2 >> 1][(j2 & 1)];
                uint32_t b1 = bfr[j2 >> 1][(j2 & 1) + 2];
                #pragma unroll
                for (int i2 = 0; i2 < 2; i2++)
                    mma_fp16(acc[i2][j2], afr[i2], b0, b1);
            }
        }

        if (kt == 3) {
            #pragma unroll
            for (int i2 = 0; i2 < 2; i2++) {
                int lr0 = wm * 32 + i2 * 16 + g;
                int o0  = mt2 * 128 + lr0;
                int o1  = o0 + 8;
                float bi0 = bias[o0], bi1 = bias[o1];
                float slo = 0.f, slo2 = 0.f, shi = 0.f, shi2 = 0.f;
                #pragma unroll
                for (int j2 = 0; j2 < 8; j2++) {
                    int lc = wn * 64 + j2 * 8 + 2 * c;
                    float v0 = acc[i2][j2][0] + bi0;
                    float v1 = acc[i2][j2][1] + bi0;
                    float v2 = acc[i2][j2][2] + bi1;
                    float v3 = acc[i2][j2][3] + bi1;
                    if (MODE == 0) {
                        if (o0 < 512) {
                            v0 = (v0 > 0.f) ? (v0 + 1.f) : __expf(v0);
                            v1 = (v1 > 0.f) ? (v1 + 1.f) : __expf(v1);
                        }
                        if (o1 < 512) {
                            v2 = (v2 > 0.f) ? (v2 + 1.f) : __expf(v2);
                            v3 = (v3 > 0.f) ? (v3 + 1.f) : __expf(v3);
                        }
                        __half* Cd = g_qkvh + ((size_t)bz * MQKV + (size_t)mt2 * 128) * NSP
                                   + (size_t)nt * 128;
                        *(__half2*)(Cd + (size_t)lr0 * NSP + lc)       = __floats2half2_rn(v0, v1);
                        *(__half2*)(Cd + (size_t)(lr0 + 8) * NSP + lc) = __floats2half2_rn(v2, v3);
                    } else {
                        __half* Cd = g_projh + ((size_t)bz * CCH + (size_t)mt2 * 128) * NSP
                                   + (size_t)nt * 128;
                        *(__half2*)(Cd + (size_t)lr0 * NSP + lc)       = __floats2half2_rn(v0, v1);
                        *(__half2*)(Cd + (size_t)(lr0 + 8) * NSP + lc) = __floats2half2_rn(v2, v3);
                        slo += v0 + v1;  slo2 += v0 * v0 + v1 * v1;
                        shi += v2 + v3;  shi2 += v2 * v2 + v3 * v3;
                    }
                    #pragma unroll
                    for (int q = 0; q < 4; q++) acc[i2][j2][q] = 0.f;
                }
                if (MODE == 1) {
                    slo = warp_sum(slo);  slo2 = warp_sum(slo2);
                    shi = warp_sum(shi);  shi2 = warp_sum(shi2);
                    if (lane == 0) {
                        int Gi = mt2 * 16 + wm * 4 + i2 * 2;
                        gnacc[wn][Gi * 2]           += slo;
                        gnacc[wn][Gi * 2 + 1]       += slo2;
                        gnacc[wn][(Gi + 1) * 2]     += shi;
                        gnacc[wn][(Gi + 1) * 2 + 1] += shi2;
                    }
                }
            }
        }

        __syncthreads();
        if (G + 2 < NG) load_A();
        else            cp_commit();
    }

    if (MODE == 1) {
        __syncthreads();
        if (t < 64)
            g_gnpart[((size_t)bz * 256 + nt) * 64 + t] = gnacc[0][t] + gnacc[1][t];
    }
}

// ---------------- kv = k·v^T via tensor cores, single-wave grid, 8-slice pipeline ----
#define KVSLICE 16896
#define KVSTAGE (2 * KVSLICE)
#define KVSMEM  (2 * KVSTAGE)

__global__ void __launch_bounds__(256, 2) kv_mma_kernel() {
    extern __shared__ char sm[];
    const uint32_t sb = smem_u32(sm);

    int bh = blockIdx.x, split = blockIdx.y;
    int b = bh >> 3, h = bh & 7;

    const int t = threadIdx.x;
    const int lane = t & 31, w = t >> 5;
    const int g = lane >> 2, c = lane & 3;

    const __half* kbase = g_qkvh + ((size_t)b * MQKV + 256 + h * HD) * NSP + (size_t)split * 2048;
    const __half* vbase = g_qkvh + ((size_t)b * MQKV + 512 + h * HD) * NSP + (size_t)split * 2048;

    auto load_slice = [&](int sl) {
        int st = sl & 1;
        uint32_t kd = sb + (uint32_t)st * KVSTAGE;
        uint32_t vd = kd + KVSLICE;
        #pragma unroll
        for (int i = 0; i < 4; i++) {
            int f = t + i * 256;
            int r = f >> 5, c32 = f & 31;
            cp16(kd + (uint32_t)(r * 528 + c32 * 16),
                 kbase + (size_t)r * NSP + sl * 256 + c32 * 8);
            cp16(vd + (uint32_t)(r * 528 + c32 * 16),
                 vbase + (size_t)r * NSP + sl * 256 + c32 * 8);
        }
        cp_commit();
    };
    load_slice(0);
    load_slice(1);

    int row_lo = (lane & 7) + ((lane >> 3) & 1) * 8;
    int ksel = lane >> 4;
    uint32_t kbyte = (uint32_t)(w * 64 + ksel * 16);

    float acc[2][4][4];
    #pragma unroll
    for (int i = 0; i < 2; i++)
        #pragma unroll
        for (int j = 0; j < 4; j++)
            #pragma unroll
            for (int q = 0; q < 4; q++) acc[i][j][q] = 0.f;
    float rsum = 0.f;
    const int rr = t >> 3, seg = t & 7;

    #pragma unroll 1
    for (int sl = 0; sl < 8; sl++) {
        int st = sl & 1;
        uint32_t kB = sb + (uint32_t)st * KVSTAGE;
        uint32_t vB = kB + KVSLICE;

        cp_wait1();
        __syncthreads();

        const __half* krow = (const __half*)(sm + (size_t)st * KVSTAGE) + rr * 264;
        #pragma unroll
        for (int j = 0; j < 16; j++) {
            float2 kf = __half22float2(*(const __half2*)(krow + seg * 32 + 2 * j));
            rsum += kf.x + kf.y;
        }

        #pragma unroll
        for (int kg = 0; kg < 2; kg++) {
            uint32_t afr[2][4], bfr[2][4];
            #pragma unroll
            for (int i2 = 0; i2 < 2; i2++)
                ldm_x4(afr[i2], kB + (uint32_t)((i2 * 16 + row_lo) * 528) + kbyte + kg * 32);
            #pragma unroll
            for (int j4 = 0; j4 < 2; j4++)
                ldm_x4(bfr[j4], vB + (uint32_t)((j4 * 16 + row_lo) * 528) + kbyte + kg * 32);
            #pragma unroll
            for (int j = 0; j < 4; j++) {
                uint32_t b0 = bfr[j >> 1][(j & 1)];
                uint32_t b1 = bfr[j >> 1][(j & 1) + 2];
                #pragma unroll
                for (int i2 = 0; i2 < 2; i2++)
                    mma_fp16(acc[i2][j], afr[i2], b0, b1);
            }
        }

        __syncthreads();
        if (sl + 2 < 8) load_slice(sl + 2);
        else            cp_commit();
    }

    {
        float s = rsum;
        #pragma unroll
        for (int o = 4; o; o >>= 1) s += __shfl_xor_sync(0xffffffffu, s, o);
        if (seg == 0) g_ksump[(split * 16 + bh) * 32 + rr] = s;
    }
    __syncthreads();

    float* red = (float*)sm;
    #pragma unroll
    for (int i2 = 0; i2 < 2; i2++)
        #pragma unroll
        for (int j = 0; j < 4; j++) {
            int r0 = i2 * 16 + g, cc = j * 8 + 2 * c;
            red[w * 1024 + r0 * 32 + cc]           = acc[i2][j][0];
            red[w * 1024 + r0 * 32 + cc + 1]       = acc[i2][j][1];
            red[w * 1024 + (r0 + 8) * 32 + cc]     = acc[i2][j][2];
            red[w * 1024 + (r0 + 8) * 32 + cc + 1] = acc[i2][j][3];
        }
    __syncthreads();

    #pragma unroll
    for (int u = 0; u < 4; u++) {
        int de = t * 4 + u;
        float s = 0.f;
        #pragma unroll
        for (int ww = 0; ww < 8; ww++) s += red[ww * 1024 + de];
        g_kvpart[((size_t)split * 16 + bh) * 1024 + de] = s;
    }
}

// reduce kv partials + rowsums
__global__ void kvreduce_kernel() {
    int i = blockIdx.x * 256 + threadIdx.x;
    if (i >= 16 * 1024) return;
    int bh = i >> 10, de = i & 1023;
    int d = de >> 5, e = de & 31;
    float rs = 0.f;
    #pragma unroll
    for (int sp = 0; sp < KVS; sp++)
        rs += g_ksump[(sp * 16 + bh) * 32 + d];
    float cs = fmaxf(rs, 1e-6f);
    float inv = 1.0f / cs;
    float s = 0.f;
    #pragma unroll
    for (int sp = 0; sp < KVS; sp++)
        s += g_kvpart[((size_t)sp * 16 + bh) * 1024 + de];
    g_kv[i] = s * inv;
    if (e == 0) {
        int b = bh >> 3, h = bh & 7;
        g_ksumA[b * CCH + h * HD + d] = rs * inv;
    }
}

// ---------------- W2 = ow @ blockdiag(kv)^T ----------------
__global__ void w2prep_kernel(const float* __restrict__ out_w) {
    int o = blockIdx.x, b = blockIdx.y;
    int t = threadIdx.x;
    __shared__ float owrow[256];
    owrow[t] = out_w[o * CCH + t];
    __syncthreads();
    int h = t >> 5, d = t & 31;
    const float* kvp = g_kv + (b * 8 + h) * 1024 + d * 32;
    const float* owp = owrow + h * 32;
    float s = 0.f;
    #pragma unroll
    for (int e = 0; e < 32; e++) s = fmaf(owp[e], kvp[e], s);
    g_w2h[((size_t)b * CCH + o) * CCH + t] = __float2half_rn(s);
}

// ---------------- final: y = xh + GN2(proj), GN2 stats inline ----------------
__global__ void __launch_bounds__(256) final_kernel(
    const float* __restrict__ ow, const float* __restrict__ ob,
    float* __restrict__ out)
{
    const int n4 = NSP / 4;
    size_t base = (size_t)blockIdx.x * 1024;
    int row = (int)(base / n4);
    int c = row % CCH, b = row / CCH;
    int gg = c / CPG;

    float s  = g_gnpart[((size_t)b * 256 + threadIdx.x) * 64 + gg * 2];
    float s2 = g_gnpart[((size_t)b * 256 + threadIdx.x) * 64 + gg * 2 + 1];
    __shared__ float sh1[8], sh2[8];
    __shared__ float bc[2];
    s = warp_sum(s); s2 = warp_sum(s2);
    int w = threadIdx.x >> 5, l = threadIdx.x & 31;
    if (l == 0) { sh1[w] = s; sh2[w] = s2; }
    __syncthreads();
    if (threadIdx.x == 0) {
        float ts = 0.f, ts2 = 0.f;
        #pragma unroll
        for (int i = 0; i < 8; i++) { ts += sh1[i]; ts2 += sh2[i]; }
        const float invn = 1.0f / (float)(CPG * NSP);
        float mu = ts * invn;
        float r  = rsqrtf(ts2 * invn - mu * mu + EPS);
        float sc = r * ow[c];
        bc[0] = sc;
        bc[1] = ob[c] - mu * sc;
    }
    __syncthreads();
    float sc = bc[0], shf = bc[1];

    const __half2* ph = (const __half2*)g_projh;
    const __half2* xh = (const __half2*)g_xh;
    #pragma unroll
    for (int u = 0; u < 4; u++) {
        size_t i = base + u * 256 + threadIdx.x;
        float2 x0 = __half22float2(xh[2 * i]);
        float2 x1 = __half22float2(xh[2 * i + 1]);
        float2 p0 = __half22float2(ph[2 * i]);
        float2 p1 = __half22float2(ph[2 * i + 1]);
        float4 o;
        o.x = x0.x + fmaf(p0.x, sc, shf);
        o.y = x0.y + fmaf(p0.y, sc, shf);
        o.z = x1.x + fmaf(p1.x, sc, shf);
        o.w = x1.y + fmaf(p1.y, sc, shf);
        ((float4*)out)[i] = o;
    }
}

// ---------------- launch ----------------
extern "C" void kernel_launch(void* const* d_in, const int* in_sizes, int n_in,
                              void* d_out, int out_size) {
    const float* x      = (const float*)d_in[0];
    const float* norm_w = (const float*)d_in[1];
    const float* norm_b = (const float*)d_in[2];
    const float* qkv_w  = (const float*)d_in[3];
    const float* qkv_b  = (const float*)d_in[4];
    const float* out_w  = (const float*)d_in[5];
    const float* out_b  = (const float*)d_in[6];
    const float* onw    = (const float*)d_in[7];
    const float* onb    = (const float*)d_in[8];
    float* out = (float*)d_out;

    cudaFuncSetAttribute(mma_gemm_kernel<0>, cudaFuncAttributeMaxDynamicSharedMemorySize, GSMEM);
    cudaFuncSetAttribute(mma_gemm_kernel<1>, cudaFuncAttributeMaxDynamicSharedMemorySize, GSMEM);
    cudaFuncSetAttribute(kv_mma_kernel, cudaFuncAttributeMaxDynamicSharedMemorySize, KVSMEM);

    gn_stats0_kernel<<<dim3(BATCH * GRP, 4), 256>>>(x);
    prep2_kernel<<<dim3(MQKV, BATCH), 256>>>(qkv_w, qkv_b, norm_w, norm_b);
    mma_gemm_kernel<0><<<dim3(256, 1, BATCH), 256, GSMEM>>>(nullptr);
    kv_mma_kernel<<<dim3(16, KVS), 256, KVSMEM>>>();
    kvreduce_kernel<<<64, 256>>>();
    w2prep_kernel<<<dim3(CCH, BATCH), 256>>>(out_w);
    mma_gemm_kernel<1><<<dim3(256, 1, BATCH), 256, GSMEM>>>(out_b);
    final_kernel<<<4096, 256>>>(onw, onb, out);
}